// round 15
// baseline (speedup 1.0000x reference)
#include <cuda_runtime.h>
#include <cuda_fp16.h>

#define N_NODES 50000
#define N_EDGES 800000
#define D 128
#define CAP 96        // slots per row; P(Poisson(16) >= 96) ~ 1e-40

#define TM 128                                            // GEMM rows per block
#define GEMM_BLOCKS ((N_NODES + TM - 1) / TM)             // 391
#define EDGE_BLOCKS ((N_EDGES / 4 + 255) / 256)           // 782
#define WPITCH 136   // halves; conflict-free b-fragment LDS

// Scratch (static __device__ per allocation rules; zero-initialized at load)
__device__ __half g_H[N_NODES * D];       // h = x @ W in fp16  (12.8 MB)
__device__ __half g_WT[D * D];            // W^T in fp16, [n][k]
__device__ int    g_count[N_NODES];       // self-cleaned by spmm each invocation
__device__ int2   g_edge[N_NODES * CAP];  // {val_bits, col} bucketed by row (38.4 MB)

// ---------------------------------------------------------------------------
// W transpose/convert: g_WT[n][k] = fp16(W[k][n]).  8 blocks x 256 thr.
// ---------------------------------------------------------------------------
__global__ void wconv_kernel(const float* __restrict__ W) {
    int base = (blockIdx.x * 256 + threadIdx.x) * 8;
#pragma unroll
    for (int i = 0; i < 8; i++) {
        int idx = base + i;               // linear over g_WT [n*128+k]
        int n = idx >> 7, k = idx & 127;
        g_WT[idx] = __float2half_rn(W[k * D + n]);
    }
}

// ---------------------------------------------------------------------------
// FAT kernel: blocks [0, GEMM_BLOCKS): tensor GEMM (round-12 proven core);
//             blocks [GEMM_BLOCKS, +EDGE_BLOCKS): edge scatter into slots.
// Scatter: rank = atomicAdd(count[row]); g_edge[row*CAP + rank] = {val, col}.
// No scan, no second pass.
// ---------------------------------------------------------------------------
__global__ void __launch_bounds__(256)
gemm_scatter_kernel(const float* __restrict__ X,
                    const int* __restrict__ row,
                    const int* __restrict__ col,
                    const float* __restrict__ vals) {
    __shared__ __half sW[D][WPITCH];      // W^T whole: [n][k]
    const int tid = threadIdx.x;

    if (blockIdx.x < GEMM_BLOCKS) {
        const int wid  = tid >> 5;
        const int lane = tid & 31;
        const int g    = lane >> 2;       // 0..7
        const int t4   = lane & 3;        // 0..3
        const int block_m = blockIdx.x * TM;
        const int wrow = wid * 16;

        // stage full W^T (16384 halves = 2048 uint4) once
#pragma unroll
        for (int i = 0; i < 8; i++) {
            int u = tid + i * 256;
            int n = u >> 4;
            int kk = (u & 15) * 8;
            uint4 w = *(const uint4*)&g_WT[n * D + kk];
            *(uint4*)&sW[n][kk] = w;
        }
        __syncthreads();                  // the ONLY barrier

        int r0 = block_m + wrow + g;
        int r1 = r0 + 8;
        bool p0 = r0 < N_NODES;
        bool p1 = r1 < N_NODES;
        const float* x0 = X + (size_t)(p0 ? r0 : 0) * D;
        const float* x1 = X + (size_t)(p1 ? r1 : 0) * D;

        float c[16][4];
#pragma unroll
        for (int nt = 0; nt < 16; nt++)
#pragma unroll
            for (int j = 0; j < 4; j++) c[nt][j] = 0.f;

#pragma unroll
        for (int kt = 0; kt < 8; kt++) {
            int kb = kt * 16 + t4 * 2;
            float2 f00 = *(const float2*)&x0[kb];
            float2 f01 = *(const float2*)&x0[kb + 8];
            float2 f10 = *(const float2*)&x1[kb];
            float2 f11 = *(const float2*)&x1[kb + 8];
            __half2 ha0 = __floats2half2_rn(f00.x, f00.y);
            __half2 ha1 = __floats2half2_rn(f10.x, f10.y);
            __half2 ha2 = __floats2half2_rn(f01.x, f01.y);
            __half2 ha3 = __floats2half2_rn(f11.x, f11.y);
            unsigned a0 = *(unsigned*)&ha0;
            unsigned a1 = *(unsigned*)&ha1;
            unsigned a2 = *(unsigned*)&ha2;
            unsigned a3 = *(unsigned*)&ha3;

#pragma unroll
            for (int nt = 0; nt < 16; nt++) {
                unsigned b0 = *(unsigned*)&sW[nt * 8 + g][kt * 16 + t4 * 2];
                unsigned b1 = *(unsigned*)&sW[nt * 8 + g][kt * 16 + 8 + t4 * 2];
                asm volatile(
                    "mma.sync.aligned.m16n8k16.row.col.f32.f16.f16.f32 "
                    "{%0,%1,%2,%3}, {%4,%5,%6,%7}, {%8,%9}, {%0,%1,%2,%3};"
                    : "+f"(c[nt][0]), "+f"(c[nt][1]),
                      "+f"(c[nt][2]), "+f"(c[nt][3])
                    : "r"(a0), "r"(a1), "r"(a2), "r"(a3), "r"(b0), "r"(b1));
            }
        }

#pragma unroll
        for (int nt = 0; nt < 16; nt++) {
            int ccol = nt * 8 + t4 * 2;
            if (p0)
                *(__half2*)&g_H[(size_t)r0 * D + ccol] =
                    __floats2half2_rn(c[nt][0], c[nt][1]);
            if (p1)
                *(__half2*)&g_H[(size_t)r1 * D + ccol] =
                    __floats2half2_rn(c[nt][2], c[nt][3]);
        }
    } else {
        // ---- edge scatter (4 edges/thread, int4 in, one 8B store each) ----
        int t = (blockIdx.x - GEMM_BLOCKS) * 256 + tid;
        if (t * 4 >= N_EDGES) return;
        int4   r  = __ldg((const int4*)&row[t * 4]);
        int4   cl = __ldg((const int4*)&col[t * 4]);
        float4 v  = __ldg((const float4*)&vals[t * 4]);

        int2 e;
        int rk;
        rk = atomicAdd(&g_count[r.x], 1);
        e.x = __float_as_int(v.x); e.y = cl.x;
        g_edge[(size_t)r.x * CAP + min(rk, CAP - 1)] = e;
        rk = atomicAdd(&g_count[r.y], 1);
        e.x = __float_as_int(v.y); e.y = cl.y;
        g_edge[(size_t)r.y * CAP + min(rk, CAP - 1)] = e;
        rk = atomicAdd(&g_count[r.z], 1);
        e.x = __float_as_int(v.z); e.y = cl.z;
        g_edge[(size_t)r.z * CAP + min(rk, CAP - 1)] = e;
        rk = atomicAdd(&g_count[r.w], 1);
        e.x = __float_as_int(v.w); e.y = cl.w;
        g_edge[(size_t)r.w * CAP + min(rk, CAP - 1)] = e;
    }
}

// ---------------------------------------------------------------------------
// Fused SpMM + bias + ReLU: one warp per output row, slots [row*CAP, +count).
// 16 lanes per edge, uint4 (8 halves) per lane, two edges per step.
// Self-cleans g_count for the next graph replay.
// ---------------------------------------------------------------------------
__global__ void spmm_kernel(const float* __restrict__ bias,
                            float* __restrict__ out) {
    int warp = (blockIdx.x * blockDim.x + threadIdx.x) >> 5;
    if (warp >= N_NODES) return;
    int lane = threadIdx.x & 31;
    int half = lane >> 4;
    int sub  = lane & 15;

    int cnt = g_count[warp];
    if (cnt > CAP) cnt = CAP;
    if (lane == 0) g_count[warp] = 0;          // self-clean (cnt already read)
    const int2* ebase = &g_edge[(size_t)warp * CAP];

    float acc[8];
#pragma unroll
    for (int j = 0; j < 8; j++) acc[j] = 0.f;

    for (int p = 0; p < cnt; p += 8) {
        int2  e[4];
        uint4 h[4];
        float v[4];
#pragma unroll
        for (int u = 0; u < 4; u++) {
            int idx = p + u * 2 + half;
            int idxc = (idx < cnt) ? idx : p;
            e[u] = __ldg(&ebase[idxc]);
            v[u] = (idx < cnt) ? __int_as_float(e[u].x) : 0.f;
        }
#pragma unroll
        for (int u = 0; u < 4; u++)
            h[u] = __ldg((const uint4*)&g_H[(size_t)e[u].y * D + sub * 8]);
#pragma unroll
        for (int u = 0; u < 4; u++) {
            float2 f0 = __half22float2(*(__half2*)&h[u].x);
            float2 f1 = __half22float2(*(__half2*)&h[u].y);
            float2 f2 = __half22float2(*(__half2*)&h[u].z);
            float2 f3 = __half22float2(*(__half2*)&h[u].w);
            acc[0] += v[u] * f0.x; acc[1] += v[u] * f0.y;
            acc[2] += v[u] * f1.x; acc[3] += v[u] * f1.y;
            acc[4] += v[u] * f2.x; acc[5] += v[u] * f2.y;
            acc[6] += v[u] * f3.x; acc[7] += v[u] * f3.y;
        }
    }

#pragma unroll
    for (int j = 0; j < 8; j++)
        acc[j] += __shfl_xor_sync(0xffffffffu, acc[j], 16);

    if (half == 0) {
        float4 b0 = *(const float4*)&bias[sub * 8];
        float4 b1 = *(const float4*)&bias[sub * 8 + 4];
        float4 r0, r1;
        r0.x = fmaxf(acc[0] + b0.x, 0.f);
        r0.y = fmaxf(acc[1] + b0.y, 0.f);
        r0.z = fmaxf(acc[2] + b0.z, 0.f);
        r0.w = fmaxf(acc[3] + b0.w, 0.f);
        r1.x = fmaxf(acc[4] + b1.x, 0.f);
        r1.y = fmaxf(acc[5] + b1.y, 0.f);
        r1.z = fmaxf(acc[6] + b1.z, 0.f);
        r1.w = fmaxf(acc[7] + b1.w, 0.f);
        *(float4*)&out[(size_t)warp * D + sub * 8]     = r0;
        *(float4*)&out[(size_t)warp * D + sub * 8 + 4] = r1;
    }
}

// ---------------------------------------------------------------------------
// Launch: 3 kernels total
// ---------------------------------------------------------------------------
extern "C" void kernel_launch(void* const* d_in, const int* in_sizes, int n_in,
                              void* d_out, int out_size) {
    const float* x      = (const float*)d_in[0];   // [50000,128]
    const float* weight = (const float*)d_in[1];   // [128,128]
    const float* bias   = (const float*)d_in[2];   // [128]
    const float* vals   = (const float*)d_in[3];   // [800000]
    const int*   row    = (const int*)d_in[4];     // [800000]
    const int*   col    = (const int*)d_in[5];     // [800000]
    float* out = (float*)d_out;                    // [50000,128]

    // 1) W^T fp16 (GEMM prerequisite)
    wconv_kernel<<<8, 256>>>(weight);

    // 2) GEMM co-scheduled with single-pass edge scatter (no scan, no permute)
    gemm_scatter_kernel<<<GEMM_BLOCKS + EDGE_BLOCKS, 256>>>(x, row, col, vals);

    // 3) fused SpMM + bias + ReLU (self-cleans g_count)
    spmm_kernel<<<(N_NODES + 7) / 8, 256>>>(bias, out);
}

// round 17
// speedup vs baseline: 2.1563x; 2.1563x over previous
#include <cuda_runtime.h>
#include <cuda_fp16.h>

#define N_NODES 50000
#define N_EDGES 800000
#define D 128

#define SCAN_B 256
#define SCAN_BLOCKS ((N_NODES + SCAN_B - 1) / SCAN_B)   // 196

#define TM 128                                            // GEMM rows per block
#define GEMM_BLOCKS ((N_NODES + TM - 1) / TM)             // 391
#define HIST_BLOCKS ((N_EDGES / 4 + 255) / 256)           // 782
#define WCONV_BLOCKS 64
#define WPITCH 136   // halves; conflict-free b-fragment LDS

// Scratch (static __device__ per allocation rules; zero-initialized at load)
__device__ __half g_H[N_NODES * D];       // h = x @ W in fp16  (12.8 MB)
__device__ __half g_WT[D * D];            // W^T in fp16, [n][k]
__device__ int    g_count[N_NODES];       // self-cleaned by scan_apply
__device__ int    g_start[N_NODES + 1];
__device__ int    g_rank[N_EDGES];        // edge rank within its row
__device__ int    g_bsum[SCAN_BLOCKS];    // per-scan-block sums; cleaned by permute
__device__ int2   g_edge[N_EDGES];        // {val_bits, col} sorted by row (6.4 MB)

// ---------------------------------------------------------------------------
// Launch 1: histogram + rank + per-bucket sums  ||  W transpose/convert.
// Hist blocks aggregate bucket (row>>8) counts in smem -> <=196 global atomics.
// ---------------------------------------------------------------------------
__global__ void hist_wconv_kernel(const int* __restrict__ row,
                                  const float* __restrict__ W) {
    __shared__ int sbin[SCAN_BLOCKS];
    const int tid = threadIdx.x;

    if (blockIdx.x < HIST_BLOCKS) {
        // init smem bins (196 < 256)
        if (tid < SCAN_BLOCKS) sbin[tid] = 0;
        __syncthreads();

        int t = blockIdx.x * 256 + tid;
        bool act = (t * 4 < N_EDGES);
        if (act) {
            int4 r = __ldg((const int4*)&row[t * 4]);
            int4 rk;
            rk.x = atomicAdd(&g_count[r.x], 1);
            rk.y = atomicAdd(&g_count[r.y], 1);
            rk.z = atomicAdd(&g_count[r.z], 1);
            rk.w = atomicAdd(&g_count[r.w], 1);
            *(int4*)&g_rank[t * 4] = rk;
            atomicAdd(&sbin[r.x >> 8], 1);
            atomicAdd(&sbin[r.y >> 8], 1);
            atomicAdd(&sbin[r.z >> 8], 1);
            atomicAdd(&sbin[r.w >> 8], 1);
        }
        __syncthreads();
        if (tid < SCAN_BLOCKS && sbin[tid])
            atomicAdd(&g_bsum[tid], sbin[tid]);
    } else {
        // W transpose/convert: one element per thread (64 blocks x 256 = 16384)
        int idx = (blockIdx.x - HIST_BLOCKS) * 256 + tid;
        int n = idx >> 7, k = idx & 127;
        g_WT[idx] = __float2half_rn(W[k * D + n]);
    }
}

// ---------------------------------------------------------------------------
// Launch 2 FAT: blocks [0, GEMM_BLOCKS): tensor GEMM (round-12 proven core);
//               blocks [GEMM_BLOCKS, +SCAN_BLOCKS): scan-apply.
// scan-apply: inline top-scan of the 196 bucket sums, then intra-block
// exclusive scan of 256 counters -> g_start. Self-cleans g_count.
// ---------------------------------------------------------------------------
__global__ void __launch_bounds__(256)
gemm_apply_kernel(const float* __restrict__ X) {
    __shared__ __half sW[D][WPITCH];      // GEMM: W^T whole (34.8 KB)
    __shared__ int s[SCAN_B];             // apply: counter scan
    __shared__ int sb[SCAN_B];            // apply: bucket-sum scan
    const int tid = threadIdx.x;

    if (blockIdx.x < GEMM_BLOCKS) {
        const int wid  = tid >> 5;
        const int lane = tid & 31;
        const int g    = lane >> 2;       // 0..7
        const int t4   = lane & 3;        // 0..3
        const int block_m = blockIdx.x * TM;
        const int wrow = wid * 16;

        // stage full W^T (16384 halves = 2048 uint4) once
#pragma unroll
        for (int i = 0; i < 8; i++) {
            int u = tid + i * 256;
            int n = u >> 4;
            int kk = (u & 15) * 8;
            uint4 w = *(const uint4*)&g_WT[n * D + kk];
            *(uint4*)&sW[n][kk] = w;
        }
        __syncthreads();                  // the ONLY barrier in this branch

        int r0 = block_m + wrow + g;
        int r1 = r0 + 8;
        bool p0 = r0 < N_NODES;
        bool p1 = r1 < N_NODES;
        const float* x0 = X + (size_t)(p0 ? r0 : 0) * D;
        const float* x1 = X + (size_t)(p1 ? r1 : 0) * D;

        float c[16][4];
#pragma unroll
        for (int nt = 0; nt < 16; nt++)
#pragma unroll
            for (int j = 0; j < 4; j++) c[nt][j] = 0.f;

#pragma unroll
        for (int kt = 0; kt < 8; kt++) {
            int kb = kt * 16 + t4 * 2;
            float2 f00 = *(const float2*)&x0[kb];
            float2 f01 = *(const float2*)&x0[kb + 8];
            float2 f10 = *(const float2*)&x1[kb];
            float2 f11 = *(const float2*)&x1[kb + 8];
            __half2 ha0 = __floats2half2_rn(f00.x, f00.y);
            __half2 ha1 = __floats2half2_rn(f10.x, f10.y);
            __half2 ha2 = __floats2half2_rn(f01.x, f01.y);
            __half2 ha3 = __floats2half2_rn(f11.x, f11.y);
            unsigned a0 = *(unsigned*)&ha0;
            unsigned a1 = *(unsigned*)&ha1;
            unsigned a2 = *(unsigned*)&ha2;
            unsigned a3 = *(unsigned*)&ha3;

#pragma unroll
            for (int nt = 0; nt < 16; nt++) {
                unsigned b0 = *(unsigned*)&sW[nt * 8 + g][kt * 16 + t4 * 2];
                unsigned b1 = *(unsigned*)&sW[nt * 8 + g][kt * 16 + 8 + t4 * 2];
                asm volatile(
                    "mma.sync.aligned.m16n8k16.row.col.f32.f16.f16.f32 "
                    "{%0,%1,%2,%3}, {%4,%5,%6,%7}, {%8,%9}, {%0,%1,%2,%3};"
                    : "+f"(c[nt][0]), "+f"(c[nt][1]),
                      "+f"(c[nt][2]), "+f"(c[nt][3])
                    : "r"(a0), "r"(a1), "r"(a2), "r"(a3), "r"(b0), "r"(b1));
            }
        }

#pragma unroll
        for (int nt = 0; nt < 16; nt++) {
            int ccol = nt * 8 + t4 * 2;
            if (p0)
                *(__half2*)&g_H[(size_t)r0 * D + ccol] =
                    __floats2half2_rn(c[nt][0], c[nt][1]);
            if (p1)
                *(__half2*)&g_H[(size_t)r1 * D + ccol] =
                    __floats2half2_rn(c[nt][2], c[nt][3]);
        }
    } else {
        // -------- scan-apply (256 threads over 256 counters) ---------------
        const int bid2 = blockIdx.x - GEMM_BLOCKS;     // 0..195

        sb[tid] = (tid < SCAN_BLOCKS) ? g_bsum[tid] : 0;
        __syncthreads();
#pragma unroll
        for (int off = 1; off < SCAN_B; off <<= 1) {
            int t = (tid >= off) ? sb[tid - off] : 0;
            __syncthreads();
            sb[tid] += t;                  // inclusive scan of bucket sums
            __syncthreads();
        }
        int boff = (bid2 == 0) ? 0 : sb[bid2 - 1];

        int i = bid2 * SCAN_B + tid;
        int c = (i < N_NODES) ? g_count[i] : 0;
        s[tid] = c;
        __syncthreads();
#pragma unroll
        for (int off = 1; off < SCAN_B; off <<= 1) {
            int t = (tid >= off) ? s[tid - off] : 0;
            __syncthreads();
            s[tid] += t;
            __syncthreads();
        }
        if (i < N_NODES) {
            g_start[i] = boff + s[tid] - c;   // exclusive prefix
            g_count[i] = 0;                   // self-clean
        }
        if (bid2 == 0 && tid == 0) g_start[N_NODES] = N_EDGES;
    }
}

// ---------------------------------------------------------------------------
// Launch 3: permute (atomic-free): pos = g_start[row] + rank.
// Also cleans g_bsum for the next invocation.
// ---------------------------------------------------------------------------
__global__ void permute_kernel(const int* __restrict__ row,
                               const int* __restrict__ col,
                               const float* __restrict__ vals) {
    if (blockIdx.x == 0 && threadIdx.x < SCAN_BLOCKS)
        g_bsum[threadIdx.x] = 0;           // self-clean (consumed last launch)

    int t = blockIdx.x * 256 + threadIdx.x;
    if (t * 4 >= N_EDGES) return;
    int4   r  = __ldg((const int4*)&row[t * 4]);
    int4   rk = *(const int4*)&g_rank[t * 4];
    int4   cl = __ldg((const int4*)&col[t * 4]);
    float4 v  = __ldg((const float4*)&vals[t * 4]);

    int2 e;
    e.x = __float_as_int(v.x); e.y = cl.x;
    g_edge[__ldg(&g_start[r.x]) + rk.x] = e;
    e.x = __float_as_int(v.y); e.y = cl.y;
    g_edge[__ldg(&g_start[r.y]) + rk.y] = e;
    e.x = __float_as_int(v.z); e.y = cl.z;
    g_edge[__ldg(&g_start[r.z]) + rk.z] = e;
    e.x = __float_as_int(v.w); e.y = cl.w;
    g_edge[__ldg(&g_start[r.w]) + rk.w] = e;
}

// ---------------------------------------------------------------------------
// Launch 4: fused CSR SpMM + bias + ReLU: one warp per output row.
// 16 lanes per edge, uint4 (8 halves) per lane, two edges per step.
// ---------------------------------------------------------------------------
__global__ void spmm_kernel(const float* __restrict__ bias,
                            float* __restrict__ out) {
    int warp = (blockIdx.x * blockDim.x + threadIdx.x) >> 5;
    if (warp >= N_NODES) return;
    int lane = threadIdx.x & 31;
    int half = lane >> 4;
    int sub  = lane & 15;

    int p   = g_start[warp];
    int end = g_start[warp + 1];

    float acc[8];
#pragma unroll
    for (int j = 0; j < 8; j++) acc[j] = 0.f;

    for (; p < end; p += 8) {
        int2  e[4];
        uint4 h[4];
        float v[4];
#pragma unroll
        for (int u = 0; u < 4; u++) {
            int idx = p + u * 2 + half;
            int idxc = (idx < end) ? idx : p;
            e[u] = __ldg(&g_edge[idxc]);
            v[u] = (idx < end) ? __int_as_float(e[u].x) : 0.f;
        }
#pragma unroll
        for (int u = 0; u < 4; u++)
            h[u] = __ldg((const uint4*)&g_H[(size_t)e[u].y * D + sub * 8]);
#pragma unroll
        for (int u = 0; u < 4; u++) {
            float2 f0 = __half22float2(*(__half2*)&h[u].x);
            float2 f1 = __half22float2(*(__half2*)&h[u].y);
            float2 f2 = __half22float2(*(__half2*)&h[u].z);
            float2 f3 = __half22float2(*(__half2*)&h[u].w);
            acc[0] += v[u] * f0.x; acc[1] += v[u] * f0.y;
            acc[2] += v[u] * f1.x; acc[3] += v[u] * f1.y;
            acc[4] += v[u] * f2.x; acc[5] += v[u] * f2.y;
            acc[6] += v[u] * f3.x; acc[7] += v[u] * f3.y;
        }
    }

#pragma unroll
    for (int j = 0; j < 8; j++)
        acc[j] += __shfl_xor_sync(0xffffffffu, acc[j], 16);

    if (half == 0) {
        float4 b0 = *(const float4*)&bias[sub * 8];
        float4 b1 = *(const float4*)&bias[sub * 8 + 4];
        float4 r0, r1;
        r0.x = fmaxf(acc[0] + b0.x, 0.f);
        r0.y = fmaxf(acc[1] + b0.y, 0.f);
        r0.z = fmaxf(acc[2] + b0.z, 0.f);
        r0.w = fmaxf(acc[3] + b0.w, 0.f);
        r1.x = fmaxf(acc[4] + b1.x, 0.f);
        r1.y = fmaxf(acc[5] + b1.y, 0.f);
        r1.z = fmaxf(acc[6] + b1.z, 0.f);
        r1.w = fmaxf(acc[7] + b1.w, 0.f);
        *(float4*)&out[(size_t)warp * D + sub * 8]     = r0;
        *(float4*)&out[(size_t)warp * D + sub * 8 + 4] = r1;
    }
}

// ---------------------------------------------------------------------------
// Launch: 4 kernels, each chain link dependency-minimal
// ---------------------------------------------------------------------------
extern "C" void kernel_launch(void* const* d_in, const int* in_sizes, int n_in,
                              void* d_out, int out_size) {
    const float* x      = (const float*)d_in[0];   // [50000,128]
    const float* weight = (const float*)d_in[1];   // [128,128]
    const float* bias   = (const float*)d_in[2];   // [128]
    const float* vals   = (const float*)d_in[3];   // [800000]
    const int*   row    = (const int*)d_in[4];     // [800000]
    const int*   col    = (const int*)d_in[5];     // [800000]
    float* out = (float*)d_out;                    // [50000,128]

    // 1) histogram + rank + bucket sums || W^T fp16
    hist_wconv_kernel<<<HIST_BLOCKS + WCONV_BLOCKS, 256>>>(row, weight);

    // 2) tensor GEMM || scan-apply (needs hist/wconv only)
    gemm_apply_kernel<<<GEMM_BLOCKS + SCAN_BLOCKS, 256>>>(x);

    // 3) atomic-free permute (+ g_bsum clean)
    permute_kernel<<<HIST_BLOCKS, 256>>>(row, col, vals);

    // 4) fused SpMM + bias + ReLU
    spmm_kernel<<<(N_NODES + 7) / 8, 256>>>(bias, out);
}